// round 9
// baseline (speedup 1.0000x reference)
#include <cuda_runtime.h>
#include <cuda_fp16.h>

// DifferentiableCensus: out = (1/9) * sum_{3x3, edge-clamped} sigmoid(neighbor - center)
// x: (16,3,512,512) f32 -> 48 independent 512x512 images.
//
// Round 9: batch-pair SIMD. Two IMAGES per half2 lane (same (r,c) position),
// so every diff/tanh/sum is element-wise across lanes -> the f16x2 2x is
// realized with ZERO lane-realignment instructions.
//  - sigmoid(d) = 0.5 + 0.5*tanh(d/2); signed tanh sum T; out = 0.5 + T/18.
//  - 1 thread = 4 cols x 8 rows x 2 images. Each pixel-pair edge computed
//    once (reverse = negation). tanh.approx.f16x2 -> 2.4 MUFU lane-ops/px.
//  - half2 diffs/sums, f32 epilogue (proven 1.66e-4 path in R4/R6/R7).

static constexpr int H = 512;
static constexpr int W = 512;
static constexpr int ROWS_PER_THREAD = 8;
static constexpr int BLOCK_X = 128;            // 128 threads * 4 cols = 512 cols

__device__ __forceinline__ __half2 tanh_h2(__half2 h) {
    unsigned u = *reinterpret_cast<unsigned*>(&h);
    unsigned r;
    asm("tanh.approx.f16x2 %0, %1;" : "=r"(r) : "r"(u));
    return *reinterpret_cast<__half2*>(&r);
}

// v[0]=col c0-1 (clamped), v[1..4]=c0..c0+3, v[5]=c0+4 (clamped).
// Lane lo = image A, lane hi = image B. Values prescaled by 0.5.
__device__ __forceinline__ void load_rowpair(const float* __restrict__ ra,
                                             const float* __restrict__ rb,
                                             int c0, int cl, int cr, __half2 v[6]) {
    const float4 a = __ldg(reinterpret_cast<const float4*>(ra + c0));
    const float4 b = __ldg(reinterpret_cast<const float4*>(rb + c0));
    v[0] = __floats2half2_rn(0.5f * __ldg(ra + cl), 0.5f * __ldg(rb + cl));
    v[1] = __floats2half2_rn(0.5f * a.x, 0.5f * b.x);
    v[2] = __floats2half2_rn(0.5f * a.y, 0.5f * b.y);
    v[3] = __floats2half2_rn(0.5f * a.z, 0.5f * b.z);
    v[4] = __floats2half2_rn(0.5f * a.w, 0.5f * b.w);
    v[5] = __floats2half2_rn(0.5f * __ldg(ra + cr), 0.5f * __ldg(rb + cr));
}

__global__ __launch_bounds__(BLOCK_X)
void census_kernel(const float* __restrict__ x, float* __restrict__ out) {
    const int c0  = threadIdx.x * 4;
    const int r0  = blockIdx.y * ROWS_PER_THREAD;
    const int pz  = blockIdx.z;                    // image pair 0..23

    const float* __restrict__ xa = x   + (size_t)(2 * pz)     * H * W;
    const float* __restrict__ xb = x   + (size_t)(2 * pz + 1) * H * W;
    float* __restrict__       oa = out + (size_t)(2 * pz)     * H * W;
    float* __restrict__       ob = out + (size_t)(2 * pz + 1) * H * W;

    const int cl = max(c0 - 1, 0);
    const int cr = min(c0 + 4, W - 1);

    __half2 b[6];
    load_rowpair(xa + (size_t)r0 * W, xb + (size_t)r0 * W, c0, cl, cr, b);

    // Priming carries from row r0-1 (p): S/SE/SW edge tanh + p's halo lanes.
    __half2 pS[4], pDR[4], pDL[4], pl, pr;
    {
        __half2 p[6];
        const size_t g = (size_t)max(r0 - 1, 0) * W;
        load_rowpair(xa + g, xb + g, c0, cl, cr, p);
        #pragma unroll
        for (int i = 0; i < 4; i++) {
            pS[i]  = tanh_h2(__hsub2(b[i + 1], p[i + 1]));
            pDR[i] = tanh_h2(__hsub2(b[i + 2], p[i + 1]));
            pDL[i] = tanh_h2(__hsub2(b[i],     p[i + 1]));
        }
        pl = p[0]; pr = p[5];
    }

    #pragma unroll
    for (int k = 0; k < ROWS_PER_THREAD; k++) {
        const int r = r0 + k;
        __half2 n[6];
        const size_t g = (size_t)min(r + 1, H - 1) * W;
        load_rowpair(xa + g, xb + g, c0, cl, cr, n);

        __half2 tS[4], tDR[4], tDL[4], tE[4];
        #pragma unroll
        for (int i = 0; i < 4; i++) {
            tS[i]  = tanh_h2(__hsub2(n[i + 1], b[i + 1])); // S
            tDR[i] = tanh_h2(__hsub2(n[i + 2], b[i + 1])); // SE
            tDL[i] = tanh_h2(__hsub2(n[i],     b[i + 1])); // SW
            tE[i]  = tanh_h2(__hsub2(b[i + 2], b[i + 1])); // E
        }
        const __half2 tW0  = tanh_h2(__hsub2(b[0], b[1])); // W  halo
        const __half2 tUL0 = tanh_h2(__hsub2(pl,   b[1])); // NW halo
        const __half2 tUR3 = tanh_h2(__hsub2(pr,   b[4])); // NE halo

        // Signed sums (all element-wise across the image-pair lanes).
        const __half2 T0 = __hadd2(__hadd2(__hadd2(tS[0], tDR[0]), __hsub2(tDL[0], pS[0])),
                                   __hadd2(__hadd2(tE[0], tW0),    __hsub2(tUL0,   pDL[1])));
        const __half2 T1 = __hadd2(__hadd2(__hadd2(tS[1], tDR[1]), __hsub2(tDL[1], pS[1])),
                                   __hsub2(__hsub2(tE[1], tE[0]),  __hadd2(pDR[0], pDL[2])));
        const __half2 T2 = __hadd2(__hadd2(__hadd2(tS[2], tDR[2]), __hsub2(tDL[2], pS[2])),
                                   __hsub2(__hsub2(tE[2], tE[1]),  __hadd2(pDR[1], pDL[3])));
        const __half2 T3 = __hadd2(__hadd2(__hadd2(tS[3], tDR[3]), __hsub2(tDL[3], pS[3])),
                                   __hadd2(__hsub2(tE[3], tE[2]),  __hsub2(tUR3,   pDR[2])));

        // f32 epilogue: out = 0.5 + T/18, per image.
        float4 vA, vB;
        vA.x = fmaf(__low2float(T0),  1.0f / 18.0f, 0.5f);
        vA.y = fmaf(__low2float(T1),  1.0f / 18.0f, 0.5f);
        vA.z = fmaf(__low2float(T2),  1.0f / 18.0f, 0.5f);
        vA.w = fmaf(__low2float(T3),  1.0f / 18.0f, 0.5f);
        vB.x = fmaf(__high2float(T0), 1.0f / 18.0f, 0.5f);
        vB.y = fmaf(__high2float(T1), 1.0f / 18.0f, 0.5f);
        vB.z = fmaf(__high2float(T2), 1.0f / 18.0f, 0.5f);
        vB.w = fmaf(__high2float(T3), 1.0f / 18.0f, 0.5f);
        *reinterpret_cast<float4*>(oa + (size_t)r * W + c0) = vA;
        *reinterpret_cast<float4*>(ob + (size_t)r * W + c0) = vB;

        // Roll: keep old center row's halo lanes; carry forward edges.
        pl = b[0]; pr = b[5];
        #pragma unroll
        for (int i = 0; i < 6; i++) b[i] = n[i];
        #pragma unroll
        for (int i = 0; i < 4; i++) { pS[i] = tS[i]; pDR[i] = tDR[i]; pDL[i] = tDL[i]; }
    }
}

extern "C" void kernel_launch(void* const* d_in, const int* in_sizes, int n_in,
                              void* d_out, int out_size) {
    (void)in_sizes; (void)n_in; (void)out_size;
    const float* x = (const float*)d_in[0];
    float* out = (float*)d_out;

    dim3 block(BLOCK_X, 1, 1);
    dim3 grid(1, H / ROWS_PER_THREAD, 24);     // 24 image pairs
    census_kernel<<<grid, block>>>(x, out);
}